// round 8
// baseline (speedup 1.0000x reference)
#include <cuda_runtime.h>

#define FULLMASK 0xFFFFFFFFu
constexpr int Bb = 4, Nn = 384, Dd = 64;
constexpr int NR = Bb * Nn;
constexpr int GRAM_BLOCKS = Bb * 12 * 12;   // 576 (32x32 tiles)
constexpr int ROW_BLOCKS = NR / 8;          // 192

// dynamic smem layout (floats)
constexpr int PT_STRIDE = 385;              // 385 % 32 == 1 -> bank spread
constexpr int OFF_PT   = 0;                       // [64 * 385]
constexpr int OFF_CPW  = 64 * PT_STRIDE;          // float4 [4][64] (16B aligned)
constexpr int OFF_WKJ  = OFF_CPW + 1024;          // [4][384] floats
constexpr int OFF_JIDX = OFF_WKJ + 1536;          // ushort [4][384] = 768 floats
constexpr int DYN_FLOATS = OFF_JIDX + 768;        // FIXED: was +384 (OOB!)
constexpr int DYN_BYTES = DYN_FLOATS * 4;         // 111,872 B

__device__ float g_y2[NR];
__device__ float g_uself[NR * Dd];
__device__ float g_ci[NR * Dd];    // PRE-HALVED
__device__ float g_P[NR * Dd];     // PRE-HALVED
__device__ float g_gram[(size_t)Bb * Nn * Nn];

__device__ __forceinline__ float wred(float v) {
  #pragma unroll
  for (int o = 16; o > 0; o >>= 1) v += __shfl_xor_sync(FULLMASK, v, o);
  return v;
}
__device__ __forceinline__ float sigm(float x) { return 1.f / (1.f + __expf(-x)); }
__device__ __forceinline__ float silu_(float x) { return x * sigm(x); }
__device__ __forceinline__ float artanh_(float x) {
  x = fminf(x, 1.f - 1e-7f);
  return 0.5f * (log1pf(x) - log1pf(-x));
}
__device__ __forceinline__ float tfa(float x) {
  float y; asm("tanh.approx.f32 %0, %1;" : "=f"(y) : "f"(x)); return y;
}

// ===== k_pre: blocks [0,576) = gram 32x32 tiles; [576,768) = row precompute =====
__global__ __launch_bounds__(256)
void k_pre(const float* __restrict__ x,
           const float* __restrict__ att_w1,
           const float* __restrict__ att_b1)
{
  const int tid = threadIdx.x, w = tid >> 5, lane = tid & 31;

  if (blockIdx.x < GRAM_BLOCKS) {
    __shared__ float xis[32][65], xjs[32][65];
    const int t = blockIdx.x;
    const int b = t / 144, rr = t % 144, it = rr / 12, jt = rr % 12;
    const float* xb = x + (size_t)b * Nn * 64;
    for (int e = tid; e < 2048; e += 256) {
      const int r = e >> 6, c = e & 63;
      xis[r][c] = xb[(size_t)(it * 32 + r) * 64 + c];
      xjs[r][c] = xb[(size_t)(jt * 32 + r) * 64 + c];
    }
    __syncthreads();
    const int jj = lane, i4 = w * 4;
    float a0 = 0.f, a1 = 0.f, a2 = 0.f, a3 = 0.f;
    #pragma unroll 16
    for (int k = 0; k < 64; ++k) {
      const float xv = xjs[jj][k];
      a0 = fmaf(xis[i4 + 0][k], xv, a0);
      a1 = fmaf(xis[i4 + 1][k], xv, a1);
      a2 = fmaf(xis[i4 + 2][k], xv, a2);
      a3 = fmaf(xis[i4 + 3][k], xv, a3);
    }
    float* go = g_gram + ((size_t)(b * Nn) + it * 32 + i4) * Nn + jt * 32 + jj;
    go[0] = a0; go[Nn] = a1; go[2 * Nn] = a2; go[3 * Nn] = a3;
    return;
  }

  __shared__ float xis8[8][64];
  __shared__ float us[8][64];
  const int idx = blockIdx.x - GRAM_BLOCKS;
  const int b = idx / 48, i0 = (idx % 48) * 8;
  const float* xb = x + (size_t)b * Nn * 64;

  for (int t = tid; t < 512; t += 256)
    xis8[t >> 6][t & 63] = xb[(size_t)(i0 + (t >> 6)) * 64 + (t & 63)];
  __syncthreads();

  {
    const int r = w, gi = b * Nn + i0 + r;
    const float a0 = xis8[r][lane], a1 = xis8[r][lane + 32];
    const float x2 = wred(a0 * a0 + a1 * a1);
    const float A = 1.f - 2.f * x2 + x2;
    const float Bc = 1.f - x2;
    const float den = fmaxf(1.f - 2.f * x2 + x2 * x2, 1e-15f);
    const float inv = 1.f / den;
    const float s0 = (A * (-a0) + Bc * a0) * inv;
    const float s1 = (A * (-a1) + Bc * a1) * inv;
    const float sn = fmaxf(sqrtf(wred(s0 * s0 + s1 * s1)), 1e-15f);
    const float fac = fmaxf(Bc, 1e-15f);
    const float g = fac * artanh_(sn) / sn;
    us[r][lane] = g * s0; us[r][lane + 32] = g * s1;
    g_uself[(size_t)gi * 64 + lane] = g * s0;
    g_uself[(size_t)gi * 64 + lane + 32] = g * s1;
    if (!lane) g_y2[gi] = x2;
  }
  __syncthreads();

  {
    const int k = tid & 63, rp = tid >> 6;
    float p0 = 0.f, p1 = 0.f, c0 = att_b1[k], c1v = att_b1[k];
    #pragma unroll 8
    for (int d = 0; d < 64; ++d) {
      const float wa = att_w1[d * 64 + k];
      const float wb = att_w1[(64 + d) * 64 + k];
      p0 = fmaf(xis8[rp][d], wa, p0);
      p1 = fmaf(xis8[rp + 4][d], wa, p1);
      c0 = fmaf(us[rp][d], wb, c0);
      c1v = fmaf(us[rp + 4][d], wb, c1v);
    }
    const int g0 = b * Nn + i0 + rp, g1 = g0 + 4;
    g_P[(size_t)g0 * 64 + k] = 0.5f * p0;
    g_P[(size_t)g1 * 64 + k] = 0.5f * p1;
    g_ci[(size_t)g0 * 64 + k] = 0.5f * c0;
    g_ci[(size_t)g1 * 64 + k] = 0.5f * c1v;
  }
}

// ===== k_main: 4 rows/block, 512 threads, single 384-wide P tile =====
__global__ __launch_bounds__(512, 2)
void k_main(const float* __restrict__ x,
            const int* __restrict__ mask,
            const float* __restrict__ att_w2,
            const float* __restrict__ att_b2,
            const float* __restrict__ mlp_w1,
            const float* __restrict__ mlp_b1,
            const float* __restrict__ mlp_w2,
            const float* __restrict__ mlp_b2,
            float* __restrict__ out)
{
  extern __shared__ float smemf[];
  float* Pt = smemf + OFF_PT;                            // [64][385]
  float4* cpw = (float4*)(smemf + OFF_CPW);              // [4][64]
  float* wkj = smemf + OFF_WKJ;                          // [4][384]
  unsigned short* jidx = (unsigned short*)(smemf + OFF_JIDX); // [4][384]
  __shared__ int mcnt[4];
  __shared__ float s1p[16];

  const int tid = threadIdx.x, w = tid >> 5, lane = tid & 31;
  const int ct = blockIdx.x;
  const int b = ct / 96, i0 = (ct % 96) * 4;
  const int r = w & 3;
  const int gi = b * Nn + i0 + r;
  const float* Pbat = g_P + (size_t)(b * Nn) * 64;

  // cpw pack (threads 0-255)
  if (tid < 256) {
    const int rr = tid >> 6, k = tid & 63;
    const int gr_ = b * Nn + i0 + rr;
    cpw[rr * 64 + k] = make_float4(g_ci[(size_t)gr_ * 64 + k],
                                   g_P[(size_t)gr_ * 64 + k], att_w2[k], 0.f);
  }
  // Pt tile load: all 512 threads, coalesced LDG, conflict-free STS
  for (int t = tid; t < Nn * 64; t += 512) {
    const int j = t >> 6, k = t & 63;
    Pt[k * PT_STRIDE + j] = Pbat[(size_t)j * 64 + k];
  }
  // compaction: warps 0-3 -> rows 0-3, full 384 j's
  if (w < 4) {
    const int* mrow = mask + (size_t)(b * Nn + i0 + w) * Nn;
    int m = 0;
    #pragma unroll
    for (int sub = 0; sub < 12; ++sub) {
      const bool ok = mrow[sub * 32 + lane] != 0;
      const unsigned bal = __ballot_sync(FULLMASK, ok);
      const unsigned pre = bal & ((1u << lane) - 1u);
      if (ok) jidx[w * Nn + m + __popc(pre)] = (unsigned short)(sub * 32 + lane);
      m += __popc(bal);
    }
    if (!lane) mcnt[w] = m;
  }
  __syncthreads();

  const float x2i = g_y2[gi];
  const float omx2 = 1.f - x2i;
  const float fac = fmaxf(omx2, 1e-15f);
  const float b2v = att_b2[0];
  float S1 = 0.f;

  const int m = mcnt[r];
  const float4* cp4 = cpw + r * 64;
  const float* grow = g_gram + (size_t)gi * Nn;
  const float* y2row = g_y2 + b * Nn;

  for (int g = (w >> 2); g * 32 < m; g += 4) {
    const int idx = g * 32 + lane;
    const bool val = idx < m;
    const int jj = val ? jidx[r * Nn + idx] : 0;
    float c1 = 0.f, c2 = 0.f;
    if (val) {
      const float xy = grow[jj], y2v = y2row[jj];
      const float A = 1.f - 2.f * xy + y2v;
      const float den = fmaxf(fmaf(x2i, y2v, 1.f - 2.f * xy), 1e-15f);
      const float inv = __frcp_rn(den);
      const float t1 = fmaf(A, x2i, -omx2 * xy);
      const float t2 = fmaf(omx2, y2v, -A * xy);
      float sn = sqrtf(fmaxf(inv * inv * fmaf(A, t1, omx2 * t2), 0.f));
      sn = fminf(fmaxf(sn, 1e-15f), 1.f - 1e-7f);
      const float aos = (sn > 1e-3f)
          ? __fdividef(0.5f * __logf((1.f + sn) * __frcp_rn(1.f - sn)), sn)
          : fmaf(sn * sn, 0.33333334f, 1.f);
      const float gg = fac * aos * inv;
      c1 = -gg * A; c2 = gg * omx2;
    }
    const float* ptj = Pt + jj;
    float p0 = 0.f, p1 = 0.f, p2 = 0.f, p3 = 0.f;
    #pragma unroll 1
    for (int k = 0; k < 64; k += 4) {
      const float4 ca = cp4[k];
      const float4 cb = cp4[k + 1];
      const float4 cc = cp4[k + 2];
      const float4 cd = cp4[k + 3];
      const float ta = fmaf(c2, ptj[k * PT_STRIDE],       fmaf(c1, ca.y, ca.x));
      const float tb = fmaf(c2, ptj[(k + 1) * PT_STRIDE], fmaf(c1, cb.y, cb.x));
      const float tc = fmaf(c2, ptj[(k + 2) * PT_STRIDE], fmaf(c1, cc.y, cc.x));
      const float td = fmaf(c2, ptj[(k + 3) * PT_STRIDE], fmaf(c1, cd.y, cd.x));
      p0 = fmaf(fmaf(ta, tfa(ta), ta), ca.z, p0);
      p1 = fmaf(fmaf(tb, tfa(tb), tb), cb.z, p1);
      p2 = fmaf(fmaf(tc, tfa(tc), tc), cc.z, p2);
      p3 = fmaf(fmaf(td, tfa(td), td), cd.z, p3);
    }
    const float pr = (p0 + p1) + (p2 + p3);
    const float att = fmaf(0.5f, tfa(0.5f * (pr + b2v)), 0.5f);
    S1 = fmaf(att, c1, S1);
    if (val) wkj[r * Nn + idx] = att * c2;
  }
  {
    const float s = wred(S1);
    if (!lane) s1p[w] = s;
  }
  __syncthreads();

  // tail buffers reuse Pt region (all reads of Pt are done)
  float* supv = Pt;             // [4][64]
  float* hm2  = Pt + 256;       // [4][64]
  float* ot   = Pt + 512;       // [4][64]

  if (tid < 256) {
    const int i2 = tid >> 6, d = tid & 63;
    const int gr_ = b * Nn + i0 + i2;
    const float* xb = x + (size_t)(b * Nn) * 64;
    const int mt = mcnt[i2];
    const float* wk = wkj + i2 * Nn;
    const unsigned short* ji = jidx + i2 * Nn;
    float a0 = 0.f, a1 = 0.f, a2 = 0.f, a3 = 0.f;
    int p = 0;
    for (; p + 4 <= mt; p += 4) {
      a0 = fmaf(wk[p],     xb[(size_t)ji[p]     * 64 + d], a0);
      a1 = fmaf(wk[p + 1], xb[(size_t)ji[p + 1] * 64 + d], a1);
      a2 = fmaf(wk[p + 2], xb[(size_t)ji[p + 2] * 64 + d], a2);
      a3 = fmaf(wk[p + 3], xb[(size_t)ji[p + 3] * 64 + d], a3);
    }
    for (; p < mt; ++p)
      a0 = fmaf(wk[p], xb[(size_t)ji[p] * 64 + d], a0);
    const float S1t = (s1p[i2] + s1p[i2 + 4]) + (s1p[i2 + 8] + s1p[i2 + 12]);
    supv[i2 * 64 + d] = fmaf(S1t, x[(size_t)gr_ * 64 + d],
                             (a0 + a1) + (a2 + a3));
  }
  __syncthreads();

  if (tid < 256) {
    const int i2 = tid >> 6, k = tid & 63;
    const int gr_ = b * Nn + i0 + i2;
    float acc = mlp_b1[k];
    #pragma unroll 8
    for (int d = 0; d < 64; ++d)
      acc = fmaf(g_uself[(size_t)gr_ * 64 + d], mlp_w1[d * 64 + k], acc);
    #pragma unroll 8
    for (int d = 0; d < 64; ++d)
      acc = fmaf(supv[i2 * 64 + d], mlp_w1[(64 + d) * 64 + k], acc);
    hm2[i2 * 64 + k] = silu_(acc);
  }
  __syncthreads();
  if (tid < 256) {
    const int i2 = tid >> 6, k = tid & 63;
    const int gr_ = b * Nn + i0 + i2;
    float o = mlp_b2[k] + g_uself[(size_t)gr_ * 64 + k];
    #pragma unroll 8
    for (int d = 0; d < 64; ++d)
      o = fmaf(hm2[i2 * 64 + d], mlp_w2[d * 64 + k], o);
    ot[i2 * 64 + k] = o;
  }
  __syncthreads();

  if (w < 4) {
    const int gr_ = b * Nn + i0 + w;
    const float a0 = x[(size_t)gr_ * 64 + lane], a1 = x[(size_t)gr_ * 64 + lane + 32];
    const float xx2 = g_y2[gr_];
    const float o0 = ot[w * 64 + lane], o1 = ot[w * 64 + lane + 32];
    const float un = fmaxf(sqrtf(wred(o0 * o0 + o1 * o1)), 1e-15f);
    const float lam = 2.f / fmaxf(1.f - xx2, 1e-15f);
    const float th = tanhf(0.5f * lam * un);
    const float sc = th / un;
    const float sec0 = sc * o0, sec1 = sc * o1;
    const float xy = wred(a0 * sec0 + a1 * sec1);
    const float y2 = wred(sec0 * sec0 + sec1 * sec1);
    const float A = 1.f + 2.f * xy + y2;
    const float Bc = 1.f - xx2;
    const float den = fmaxf(1.f + 2.f * xy + xx2 * y2, 1e-15f);
    const float inv = 1.f / den;
    float r0 = (A * a0 + Bc * sec0) * inv;
    float r1 = (A * a1 + Bc * sec1) * inv;
    const float nrm = fmaxf(sqrtf(wred(r0 * r0 + r1 * r1)), 1e-15f);
    if (nrm > 0.996f) { const float s = 0.996f / nrm; r0 *= s; r1 *= s; }
    float* orow = out + (size_t)gr_ * 64;
    orow[lane] = r0; orow[lane + 32] = r1;
  }
}

extern "C" void kernel_launch(void* const* d_in, const int* in_sizes, int n_in,
                              void* d_out, int out_size)
{
  const float* x      = (const float*)d_in[0];
  const int*   mask   = (const int*)d_in[1];
  const float* att_w1 = (const float*)d_in[2];
  const float* att_b1 = (const float*)d_in[3];
  const float* att_w2 = (const float*)d_in[4];
  const float* att_b2 = (const float*)d_in[5];
  const float* mlp_w1 = (const float*)d_in[6];
  const float* mlp_b1 = (const float*)d_in[7];
  const float* mlp_w2 = (const float*)d_in[8];
  const float* mlp_b2 = (const float*)d_in[9];
  float* out = (float*)d_out;

  cudaFuncSetAttribute(k_main, cudaFuncAttributeMaxDynamicSharedMemorySize,
                       DYN_BYTES);
  k_pre<<<GRAM_BLOCKS + ROW_BLOCKS, 256>>>(x, att_w1, att_b1);
  k_main<<<Bb * (Nn / 4), 512, DYN_BYTES>>>(x, mask, att_w2, att_b2,
                                            mlp_w1, mlp_b1, mlp_w2, mlp_b2, out);
}

// round 9
// speedup vs baseline: 1.1153x; 1.1153x over previous
#include <cuda_runtime.h>
#include <cuda_fp16.h>

#define FULLMASK 0xFFFFFFFFu
constexpr int Bb = 4, Nn = 384, Dd = 64;
constexpr int NR = Bb * Nn;
constexpr int GRAM_BLOCKS = Bb * 12 * 12;   // 576
constexpr int ROW_BLOCKS = NR / 8;          // 192

// dynamic smem layout (float units)
constexpr int PTH_STRIDE = 385;                    // halves per k-row
constexpr int OFF_PTH  = 0;                        // __half[64*385] -> 12352 floats
constexpr int PTH_FLOATS = 12352;                  // 24704 halves
constexpr int OFF_CPW  = PTH_FLOATS;               // float4[4][64] = 1024 floats (16B aligned)
constexpr int OFF_WKJ  = OFF_CPW + 1024;           // float[4][384] = 1536
constexpr int OFF_JIDX = OFF_WKJ + 1536;           // ushort[4][384] = 768 floats
constexpr int DYN_FLOATS = OFF_JIDX + 768;         // 15680
constexpr int DYN_BYTES = DYN_FLOATS * 4;          // 62720 B

__device__ float g_y2[NR];
__device__ float g_uself[NR * Dd];
__device__ float g_ci[NR * Dd];    // PRE-HALVED
__device__ float g_P[NR * Dd];     // PRE-HALVED
__device__ float g_gram[(size_t)Bb * Nn * Nn];

__device__ __forceinline__ float wred(float v) {
  #pragma unroll
  for (int o = 16; o > 0; o >>= 1) v += __shfl_xor_sync(FULLMASK, v, o);
  return v;
}
__device__ __forceinline__ float sigm(float x) { return 1.f / (1.f + __expf(-x)); }
__device__ __forceinline__ float silu_(float x) { return x * sigm(x); }
__device__ __forceinline__ float artanh_(float x) {
  x = fminf(x, 1.f - 1e-7f);
  return 0.5f * (log1pf(x) - log1pf(-x));
}
__device__ __forceinline__ float tfa(float x) {
  float y; asm("tanh.approx.f32 %0, %1;" : "=f"(y) : "f"(x)); return y;
}

// ===== k_pre (unchanged from R8) =====
__global__ __launch_bounds__(256)
void k_pre(const float* __restrict__ x,
           const float* __restrict__ att_w1,
           const float* __restrict__ att_b1)
{
  const int tid = threadIdx.x, w = tid >> 5, lane = tid & 31;

  if (blockIdx.x < GRAM_BLOCKS) {
    __shared__ float xis[32][65], xjs[32][65];
    const int t = blockIdx.x;
    const int b = t / 144, rr = t % 144, it = rr / 12, jt = rr % 12;
    const float* xb = x + (size_t)b * Nn * 64;
    for (int e = tid; e < 2048; e += 256) {
      const int r = e >> 6, c = e & 63;
      xis[r][c] = xb[(size_t)(it * 32 + r) * 64 + c];
      xjs[r][c] = xb[(size_t)(jt * 32 + r) * 64 + c];
    }
    __syncthreads();
    const int jj = lane, i4 = w * 4;
    float a0 = 0.f, a1 = 0.f, a2 = 0.f, a3 = 0.f;
    #pragma unroll 16
    for (int k = 0; k < 64; ++k) {
      const float xv = xjs[jj][k];
      a0 = fmaf(xis[i4 + 0][k], xv, a0);
      a1 = fmaf(xis[i4 + 1][k], xv, a1);
      a2 = fmaf(xis[i4 + 2][k], xv, a2);
      a3 = fmaf(xis[i4 + 3][k], xv, a3);
    }
    float* go = g_gram + ((size_t)(b * Nn) + it * 32 + i4) * Nn + jt * 32 + jj;
    go[0] = a0; go[Nn] = a1; go[2 * Nn] = a2; go[3 * Nn] = a3;
    return;
  }

  __shared__ float xis8[8][64];
  __shared__ float us[8][64];
  const int idx = blockIdx.x - GRAM_BLOCKS;
  const int b = idx / 48, i0 = (idx % 48) * 8;
  const float* xb = x + (size_t)b * Nn * 64;

  for (int t = tid; t < 512; t += 256)
    xis8[t >> 6][t & 63] = xb[(size_t)(i0 + (t >> 6)) * 64 + (t & 63)];
  __syncthreads();

  {
    const int r = w, gi = b * Nn + i0 + r;
    const float a0 = xis8[r][lane], a1 = xis8[r][lane + 32];
    const float x2 = wred(a0 * a0 + a1 * a1);
    const float A = 1.f - 2.f * x2 + x2;
    const float Bc = 1.f - x2;
    const float den = fmaxf(1.f - 2.f * x2 + x2 * x2, 1e-15f);
    const float inv = 1.f / den;
    const float s0 = (A * (-a0) + Bc * a0) * inv;
    const float s1 = (A * (-a1) + Bc * a1) * inv;
    const float sn = fmaxf(sqrtf(wred(s0 * s0 + s1 * s1)), 1e-15f);
    const float fac = fmaxf(Bc, 1e-15f);
    const float g = fac * artanh_(sn) / sn;
    us[r][lane] = g * s0; us[r][lane + 32] = g * s1;
    g_uself[(size_t)gi * 64 + lane] = g * s0;
    g_uself[(size_t)gi * 64 + lane + 32] = g * s1;
    if (!lane) g_y2[gi] = x2;
  }
  __syncthreads();

  {
    const int k = tid & 63, rp = tid >> 6;
    float p0 = 0.f, p1 = 0.f, c0 = att_b1[k], c1v = att_b1[k];
    #pragma unroll 8
    for (int d = 0; d < 64; ++d) {
      const float wa = att_w1[d * 64 + k];
      const float wb = att_w1[(64 + d) * 64 + k];
      p0 = fmaf(xis8[rp][d], wa, p0);
      p1 = fmaf(xis8[rp + 4][d], wa, p1);
      c0 = fmaf(us[rp][d], wb, c0);
      c1v = fmaf(us[rp + 4][d], wb, c1v);
    }
    const int g0 = b * Nn + i0 + rp, g1 = g0 + 4;
    g_P[(size_t)g0 * 64 + k] = 0.5f * p0;
    g_P[(size_t)g1 * 64 + k] = 0.5f * p1;
    g_ci[(size_t)g0 * 64 + k] = 0.5f * c0;
    g_ci[(size_t)g1 * 64 + k] = 0.5f * c1v;
  }
}

// ===== k_main: 4 rows/block, 512 threads, fp16 P tile (384-wide) =====
__global__ __launch_bounds__(512, 2)
void k_main(const float* __restrict__ x,
            const int* __restrict__ mask,
            const float* __restrict__ att_w2,
            const float* __restrict__ att_b2,
            const float* __restrict__ mlp_w1,
            const float* __restrict__ mlp_b1,
            const float* __restrict__ mlp_w2,
            const float* __restrict__ mlp_b2,
            float* __restrict__ out)
{
  extern __shared__ float smemf[];
  __half* PtH = (__half*)(smemf + OFF_PTH);              // [64][385] halves
  float4* cpw = (float4*)(smemf + OFF_CPW);              // [4][64]
  float* wkj = smemf + OFF_WKJ;                          // [4][384]
  unsigned short* jidx = (unsigned short*)(smemf + OFF_JIDX); // [4][384]
  __shared__ int mcnt[4];
  __shared__ float s1p[16];

  const int tid = threadIdx.x, w = tid >> 5, lane = tid & 31;
  const int ct = blockIdx.x;
  const int b = ct / 96, i0 = (ct % 96) * 4;
  const int r = w & 3;
  const int gi = b * Nn + i0 + r;
  const float* Pbat = g_P + (size_t)(b * Nn) * 64;

  if (tid < 256) {
    const int rr = tid >> 6, k = tid & 63;
    const int gr_ = b * Nn + i0 + rr;
    cpw[rr * 64 + k] = make_float4(g_ci[(size_t)gr_ * 64 + k],
                                   g_P[(size_t)gr_ * 64 + k], att_w2[k], 0.f);
  }
  for (int t = tid; t < Nn * 64; t += 512) {
    const int j = t >> 6, k = t & 63;
    PtH[k * PTH_STRIDE + j] = __float2half_rn(Pbat[(size_t)j * 64 + k]);
  }
  if (w < 4) {
    const int* mrow = mask + (size_t)(b * Nn + i0 + w) * Nn;
    int m = 0;
    #pragma unroll
    for (int sub = 0; sub < 12; ++sub) {
      const bool ok = mrow[sub * 32 + lane] != 0;
      const unsigned bal = __ballot_sync(FULLMASK, ok);
      const unsigned pre = bal & ((1u << lane) - 1u);
      if (ok) jidx[w * Nn + m + __popc(pre)] = (unsigned short)(sub * 32 + lane);
      m += __popc(bal);
    }
    if (!lane) mcnt[w] = m;
  }
  __syncthreads();

  const float x2i = g_y2[gi];
  const float omx2 = 1.f - x2i;
  const float fac = fmaxf(omx2, 1e-15f);
  const float b2v = att_b2[0];
  float S1 = 0.f;

  const int m = mcnt[r];
  const float4* cp4 = cpw + r * 64;
  const float* grow = g_gram + (size_t)gi * Nn;
  const float* y2row = g_y2 + b * Nn;

  for (int g = (w >> 2); g * 32 < m; g += 4) {
    const int idx = g * 32 + lane;
    const bool val = idx < m;
    const int jj = val ? jidx[r * Nn + idx] : 0;
    float c1 = 0.f, c2 = 0.f;
    if (val) {
      const float xy = grow[jj], y2v = y2row[jj];
      const float A = 1.f - 2.f * xy + y2v;
      const float den = fmaxf(fmaf(x2i, y2v, 1.f - 2.f * xy), 1e-15f);
      const float inv = __frcp_rn(den);
      const float t1 = fmaf(A, x2i, -omx2 * xy);
      const float t2 = fmaf(omx2, y2v, -A * xy);
      float sn = sqrtf(fmaxf(inv * inv * fmaf(A, t1, omx2 * t2), 0.f));
      sn = fminf(fmaxf(sn, 1e-15f), 1.f - 1e-7f);
      const float aos = (sn > 1e-3f)
          ? __fdividef(0.5f * __logf((1.f + sn) * __frcp_rn(1.f - sn)), sn)
          : fmaf(sn * sn, 0.33333334f, 1.f);
      const float gg = fac * aos * inv;
      c1 = -gg * A; c2 = gg * omx2;
    }
    const __half* ptj = PtH + jj;
    float p0 = 0.f, p1 = 0.f, p2 = 0.f, p3 = 0.f;
    #pragma unroll 1
    for (int k = 0; k < 64; k += 4) {
      const float4 ca = cp4[k];
      const float4 cb = cp4[k + 1];
      const float4 cc = cp4[k + 2];
      const float4 cd = cp4[k + 3];
      const float ta = fmaf(c2, __half2float(ptj[k * PTH_STRIDE]),       fmaf(c1, ca.y, ca.x));
      const float tb = fmaf(c2, __half2float(ptj[(k + 1) * PTH_STRIDE]), fmaf(c1, cb.y, cb.x));
      const float tc = fmaf(c2, __half2float(ptj[(k + 2) * PTH_STRIDE]), fmaf(c1, cc.y, cc.x));
      const float td = fmaf(c2, __half2float(ptj[(k + 3) * PTH_STRIDE]), fmaf(c1, cd.y, cd.x));
      p0 = fmaf(fmaf(ta, tfa(ta), ta), ca.z, p0);
      p1 = fmaf(fmaf(tb, tfa(tb), tb), cb.z, p1);
      p2 = fmaf(fmaf(tc, tfa(tc), tc), cc.z, p2);
      p3 = fmaf(fmaf(td, tfa(td), td), cd.z, p3);
    }
    const float pr = (p0 + p1) + (p2 + p3);
    const float att = fmaf(0.5f, tfa(0.5f * (pr + b2v)), 0.5f);
    S1 = fmaf(att, c1, S1);
    if (val) wkj[r * Nn + idx] = att * c2;
  }
  {
    const float s = wred(S1);
    if (!lane) s1p[w] = s;
  }
  __syncthreads();

  // tail scratch over PtH region (all PtH reads done)
  float* sup8 = smemf;            // [8][64]
  float* supv = smemf + 512;      // [4][64]
  float* h1p  = smemf + 768;      // [8][64]
  float* hm2  = smemf + 1280;     // [4][64]
  float* ot   = smemf + 1536;     // [4][64]

  // support gather: 8 groups = (half, row); halves interleave the compact list
  {
    const int ch = tid >> 6, d = tid & 63;
    const int row = ch & 3, half = ch >> 2;
    const float* xb = x + (size_t)(b * Nn) * 64;
    const int mt = mcnt[row];
    const float* wk = wkj + row * Nn;
    const unsigned short* ji = jidx + row * Nn;
    float a0 = 0.f, a1 = 0.f, a2 = 0.f, a3 = 0.f;
    int p = half;
    for (; p + 6 < mt; p += 8) {
      a0 = fmaf(wk[p],     xb[(size_t)ji[p]     * 64 + d], a0);
      a1 = fmaf(wk[p + 2], xb[(size_t)ji[p + 2] * 64 + d], a1);
      a2 = fmaf(wk[p + 4], xb[(size_t)ji[p + 4] * 64 + d], a2);
      a3 = fmaf(wk[p + 6], xb[(size_t)ji[p + 6] * 64 + d], a3);
    }
    for (; p < mt; p += 2)
      a0 = fmaf(wk[p], xb[(size_t)ji[p] * 64 + d], a0);
    sup8[ch * 64 + d] = (a0 + a1) + (a2 + a3);
  }
  __syncthreads();

  if (tid < 256) {
    const int i2 = tid >> 6, d = tid & 63;
    const int gr_ = b * Nn + i0 + i2;
    const float S1t = (s1p[i2] + s1p[i2 + 4]) + (s1p[i2 + 8] + s1p[i2 + 12]);
    supv[i2 * 64 + d] = fmaf(S1t, x[(size_t)gr_ * 64 + d],
                             sup8[i2 * 64 + d] + sup8[(i2 + 4) * 64 + d]);
  }
  __syncthreads();

  // MLP layer1: 8 groups = (half, row); half0 = uself part (+bias), half1 = support part
  {
    const int ch = tid >> 6, k = tid & 63;
    const int row = ch & 3, half = ch >> 2;
    const int gr_ = b * Nn + i0 + row;
    float acc;
    if (half == 0) {
      acc = mlp_b1[k];
      #pragma unroll 8
      for (int d = 0; d < 64; ++d)
        acc = fmaf(g_uself[(size_t)gr_ * 64 + d], mlp_w1[d * 64 + k], acc);
    } else {
      acc = 0.f;
      #pragma unroll 8
      for (int d = 0; d < 64; ++d)
        acc = fmaf(supv[row * 64 + d], mlp_w1[(64 + d) * 64 + k], acc);
    }
    h1p[ch * 64 + k] = acc;
  }
  __syncthreads();
  if (tid < 256) {
    const int i2 = tid >> 6, k = tid & 63;
    hm2[i2 * 64 + k] = silu_(h1p[i2 * 64 + k] + h1p[(i2 + 4) * 64 + k]);
  }
  __syncthreads();
  if (tid < 256) {
    const int i2 = tid >> 6, k = tid & 63;
    const int gr_ = b * Nn + i0 + i2;
    float o = mlp_b2[k] + g_uself[(size_t)gr_ * 64 + k];
    #pragma unroll 8
    for (int d = 0; d < 64; ++d)
      o = fmaf(hm2[i2 * 64 + d], mlp_w2[d * 64 + k], o);
    ot[i2 * 64 + k] = o;
  }
  __syncthreads();

  if (w < 4) {
    const int gr_ = b * Nn + i0 + w;
    const float a0 = x[(size_t)gr_ * 64 + lane], a1 = x[(size_t)gr_ * 64 + lane + 32];
    const float xx2 = g_y2[gr_];
    const float o0 = ot[w * 64 + lane], o1 = ot[w * 64 + lane + 32];
    const float un = fmaxf(sqrtf(wred(o0 * o0 + o1 * o1)), 1e-15f);
    const float lam = 2.f / fmaxf(1.f - xx2, 1e-15f);
    const float th = tanhf(0.5f * lam * un);
    const float sc = th / un;
    const float sec0 = sc * o0, sec1 = sc * o1;
    const float xy = wred(a0 * sec0 + a1 * sec1);
    const float y2 = wred(sec0 * sec0 + sec1 * sec1);
    const float A = 1.f + 2.f * xy + y2;
    const float Bc = 1.f - xx2;
    const float den = fmaxf(1.f + 2.f * xy + xx2 * y2, 1e-15f);
    const float inv = 1.f / den;
    float r0 = (A * a0 + Bc * sec0) * inv;
    float r1 = (A * a1 + Bc * sec1) * inv;
    const float nrm = fmaxf(sqrtf(wred(r0 * r0 + r1 * r1)), 1e-15f);
    if (nrm > 0.996f) { const float s = 0.996f / nrm; r0 *= s; r1 *= s; }
    float* orow = out + (size_t)gr_ * 64;
    orow[lane] = r0; orow[lane + 32] = r1;
  }
}

extern "C" void kernel_launch(void* const* d_in, const int* in_sizes, int n_in,
                              void* d_out, int out_size)
{
  const float* x      = (const float*)d_in[0];
  const int*   mask   = (const int*)d_in[1];
  const float* att_w1 = (const float*)d_in[2];
  const float* att_b1 = (const float*)d_in[3];
  const float* att_w2 = (const float*)d_in[4];
  const float* att_b2 = (const float*)d_in[5];
  const float* mlp_w1 = (const float*)d_in[6];
  const float* mlp_b1 = (const float*)d_in[7];
  const float* mlp_w2 = (const float*)d_in[8];
  const float* mlp_b2 = (const float*)d_in[9];
  float* out = (float*)d_out;

  cudaFuncSetAttribute(k_main, cudaFuncAttributeMaxDynamicSharedMemorySize,
                       DYN_BYTES);
  k_pre<<<GRAM_BLOCKS + ROW_BLOCKS, 256>>>(x, att_w1, att_b1);
  k_main<<<Bb * (Nn / 4), 512, DYN_BYTES>>>(x, mask, att_w2, att_b2,
                                            mlp_w1, mlp_b1, mlp_w2, mlp_b2, out);
}

// round 10
// speedup vs baseline: 1.1442x; 1.0259x over previous
#include <cuda_runtime.h>
#include <cuda_fp16.h>

#define FULLMASK 0xFFFFFFFFu
constexpr int Bb = 4, Nn = 384, Dd = 64;
constexpr int NR = Bb * Nn;
constexpr int GRAM_BLOCKS = Bb * 12 * 12;   // 576
constexpr int ROW_BLOCKS = NR / 8;          // 192

// dynamic smem layout (float units)
constexpr int PTH_STRIDE = 68;                     // halves per j-row (136 B, 8B-aligned)
constexpr int OFF_PTH  = 0;                        // __half[384][68] = 13056 floats
constexpr int OFF_CIB  = 13056;                    // float[4][64]
constexpr int OFF_PIB  = OFF_CIB + 256;            // float[4][64]
constexpr int OFF_W2B  = OFF_PIB + 256;            // float[64]
constexpr int OFF_WKJ  = OFF_W2B + 64;             // float[4][384]
constexpr int OFF_JIDX = OFF_WKJ + 1536;           // ushort[4][384] = 768 floats
constexpr int DYN_FLOATS = OFF_JIDX + 768;         // 15936
constexpr int DYN_BYTES = DYN_FLOATS * 4;          // 63744 B

__device__ float g_y2[NR];
__device__ float g_uself[NR * Dd];
__device__ float g_ci[NR * Dd];    // PRE-HALVED
__device__ float g_P[NR * Dd];     // PRE-HALVED
__device__ float g_gram[(size_t)Bb * Nn * Nn];

__device__ __forceinline__ float wred(float v) {
  #pragma unroll
  for (int o = 16; o > 0; o >>= 1) v += __shfl_xor_sync(FULLMASK, v, o);
  return v;
}
__device__ __forceinline__ float sigm(float x) { return 1.f / (1.f + __expf(-x)); }
__device__ __forceinline__ float silu_(float x) { return x * sigm(x); }
__device__ __forceinline__ float artanh_(float x) {
  x = fminf(x, 1.f - 1e-7f);
  return 0.5f * (log1pf(x) - log1pf(-x));
}
__device__ __forceinline__ float tfa(float x) {
  float y; asm("tanh.approx.f32 %0, %1;" : "=f"(y) : "f"(x)); return y;
}

// ===== k_pre (unchanged) =====
__global__ __launch_bounds__(256)
void k_pre(const float* __restrict__ x,
           const float* __restrict__ att_w1,
           const float* __restrict__ att_b1)
{
  const int tid = threadIdx.x, w = tid >> 5, lane = tid & 31;

  if (blockIdx.x < GRAM_BLOCKS) {
    __shared__ float xis[32][65], xjs[32][65];
    const int t = blockIdx.x;
    const int b = t / 144, rr = t % 144, it = rr / 12, jt = rr % 12;
    const float* xb = x + (size_t)b * Nn * 64;
    for (int e = tid; e < 2048; e += 256) {
      const int r = e >> 6, c = e & 63;
      xis[r][c] = xb[(size_t)(it * 32 + r) * 64 + c];
      xjs[r][c] = xb[(size_t)(jt * 32 + r) * 64 + c];
    }
    __syncthreads();
    const int jj = lane, i4 = w * 4;
    float a0 = 0.f, a1 = 0.f, a2 = 0.f, a3 = 0.f;
    #pragma unroll 16
    for (int k = 0; k < 64; ++k) {
      const float xv = xjs[jj][k];
      a0 = fmaf(xis[i4 + 0][k], xv, a0);
      a1 = fmaf(xis[i4 + 1][k], xv, a1);
      a2 = fmaf(xis[i4 + 2][k], xv, a2);
      a3 = fmaf(xis[i4 + 3][k], xv, a3);
    }
    float* go = g_gram + ((size_t)(b * Nn) + it * 32 + i4) * Nn + jt * 32 + jj;
    go[0] = a0; go[Nn] = a1; go[2 * Nn] = a2; go[3 * Nn] = a3;
    return;
  }

  __shared__ float xis8[8][64];
  __shared__ float us[8][64];
  const int idx = blockIdx.x - GRAM_BLOCKS;
  const int b = idx / 48, i0 = (idx % 48) * 8;
  const float* xb = x + (size_t)b * Nn * 64;

  for (int t = tid; t < 512; t += 256)
    xis8[t >> 6][t & 63] = xb[(size_t)(i0 + (t >> 6)) * 64 + (t & 63)];
  __syncthreads();

  {
    const int r = w, gi = b * Nn + i0 + r;
    const float a0 = xis8[r][lane], a1 = xis8[r][lane + 32];
    const float x2 = wred(a0 * a0 + a1 * a1);
    const float A = 1.f - 2.f * x2 + x2;
    const float Bc = 1.f - x2;
    const float den = fmaxf(1.f - 2.f * x2 + x2 * x2, 1e-15f);
    const float inv = 1.f / den;
    const float s0 = (A * (-a0) + Bc * a0) * inv;
    const float s1 = (A * (-a1) + Bc * a1) * inv;
    const float sn = fmaxf(sqrtf(wred(s0 * s0 + s1 * s1)), 1e-15f);
    const float fac = fmaxf(Bc, 1e-15f);
    const float g = fac * artanh_(sn) / sn;
    us[r][lane] = g * s0; us[r][lane + 32] = g * s1;
    g_uself[(size_t)gi * 64 + lane] = g * s0;
    g_uself[(size_t)gi * 64 + lane + 32] = g * s1;
    if (!lane) g_y2[gi] = x2;
  }
  __syncthreads();

  {
    const int k = tid & 63, rp = tid >> 6;
    float p0 = 0.f, p1 = 0.f, c0 = att_b1[k], c1v = att_b1[k];
    #pragma unroll 8
    for (int d = 0; d < 64; ++d) {
      const float wa = att_w1[d * 64 + k];
      const float wb = att_w1[(64 + d) * 64 + k];
      p0 = fmaf(xis8[rp][d], wa, p0);
      p1 = fmaf(xis8[rp + 4][d], wa, p1);
      c0 = fmaf(us[rp][d], wb, c0);
      c1v = fmaf(us[rp + 4][d], wb, c1v);
    }
    const int g0 = b * Nn + i0 + rp, g1 = g0 + 4;
    g_P[(size_t)g0 * 64 + k] = 0.5f * p0;
    g_P[(size_t)g1 * 64 + k] = 0.5f * p1;
    g_ci[(size_t)g0 * 64 + k] = 0.5f * c0;
    g_ci[(size_t)g1 * 64 + k] = 0.5f * c1v;
  }
}

// ===== k_main: 4 rows/block, 512 threads, j-major fp16 P tile =====
__global__ __launch_bounds__(512, 2)
void k_main(const float* __restrict__ x,
            const int* __restrict__ mask,
            const float* __restrict__ att_w2,
            const float* __restrict__ att_b2,
            const float* __restrict__ mlp_w1,
            const float* __restrict__ mlp_b1,
            const float* __restrict__ mlp_w2,
            const float* __restrict__ mlp_b2,
            float* __restrict__ out)
{
  extern __shared__ float smemf[];
  __half* PtH = (__half*)(smemf + OFF_PTH);              // [384][68] halves, j-major
  float* cib = smemf + OFF_CIB;                          // [4][64]
  float* pib = smemf + OFF_PIB;                          // [4][64]
  float* w2b = smemf + OFF_W2B;                          // [64]
  float* wkj = smemf + OFF_WKJ;                          // [4][384]
  unsigned short* jidx = (unsigned short*)(smemf + OFF_JIDX); // [4][384]
  __shared__ int mcnt[4];
  __shared__ float s1p[16];

  const int tid = threadIdx.x, w = tid >> 5, lane = tid & 31;
  const int ct = blockIdx.x;
  const int b = ct / 96, i0 = (ct % 96) * 4;
  const int r = w & 3;
  const int gi = b * Nn + i0 + r;
  const float* Pbat = g_P + (size_t)(b * Nn) * 64;

  if (tid < 256) {
    const int rr = tid >> 6, k = tid & 63;
    const int gr_ = b * Nn + i0 + rr;
    cib[rr * 64 + k] = g_ci[(size_t)gr_ * 64 + k];
    pib[rr * 64 + k] = g_P[(size_t)gr_ * 64 + k];
    if (tid < 64) w2b[k] = att_w2[k];
  }
  // fp16 tile fill, j-major: thread -> (j, k4), float4 read, uint2 (4 halves) write
  for (int t = tid; t < Nn * 16; t += 512) {
    const int j = t >> 4, k4 = t & 15;
    const float4 pv = *(const float4*)(Pbat + (size_t)j * 64 + k4 * 4);
    const __half2 h0 = __floats2half2_rn(pv.x, pv.y);
    const __half2 h1 = __floats2half2_rn(pv.z, pv.w);
    uint2 st;
    st.x = *(const unsigned*)&h0;
    st.y = *(const unsigned*)&h1;
    *(uint2*)(PtH + j * PTH_STRIDE + k4 * 4) = st;
  }
  if (w < 4) {
    const int* mrow = mask + (size_t)(b * Nn + i0 + w) * Nn;
    int m = 0;
    #pragma unroll
    for (int sub = 0; sub < 12; ++sub) {
      const bool ok = mrow[sub * 32 + lane] != 0;
      const unsigned bal = __ballot_sync(FULLMASK, ok);
      const unsigned pre = bal & ((1u << lane) - 1u);
      if (ok) jidx[w * Nn + m + __popc(pre)] = (unsigned short)(sub * 32 + lane);
      m += __popc(bal);
    }
    if (!lane) mcnt[w] = m;
  }
  __syncthreads();

  const float x2i = g_y2[gi];
  const float omx2 = 1.f - x2i;
  const float fac = fmaxf(omx2, 1e-15f);
  const float b2v = att_b2[0];
  float S1 = 0.f;

  const int m = mcnt[r];
  const float* cibr = cib + r * 64;
  const float* pibr = pib + r * 64;
  const float* grow = g_gram + (size_t)gi * Nn;
  const float* y2row = g_y2 + b * Nn;

  for (int g = (w >> 2); g * 32 < m; g += 4) {
    const int idx = g * 32 + lane;
    const bool val = idx < m;
    const int jj = val ? jidx[r * Nn + idx] : 0;
    float c1 = 0.f, c2 = 0.f;
    if (val) {
      const float xy = grow[jj], y2v = y2row[jj];
      const float A = 1.f - 2.f * xy + y2v;
      const float den = fmaxf(fmaf(x2i, y2v, 1.f - 2.f * xy), 1e-15f);
      const float inv = __frcp_rn(den);
      const float t1 = fmaf(A, x2i, -omx2 * xy);
      const float t2 = fmaf(omx2, y2v, -A * xy);
      float sn = sqrtf(fmaxf(inv * inv * fmaf(A, t1, omx2 * t2), 0.f));
      sn = fminf(fmaxf(sn, 1e-15f), 1.f - 1e-7f);
      const float aos = (sn > 1e-3f)
          ? __fdividef(0.5f * __logf((1.f + sn) * __frcp_rn(1.f - sn)), sn)
          : fmaf(sn * sn, 0.33333334f, 1.f);
      const float gg = fac * aos * inv;
      c1 = -gg * A; c2 = gg * omx2;
    }
    const __half* prow = PtH + jj * PTH_STRIDE;   // this lane's j-row
    uint2 nv = *(const uint2*)prow;               // prefetch k=0..3
    float p0 = 0.f, p1 = 0.f, p2 = 0.f, p3 = 0.f;
    #pragma unroll 1
    for (int k = 0; k < 64; k += 4) {
      const uint2 v = nv;
      if (k + 4 < 64) nv = *(const uint2*)(prow + k + 4);   // prefetch next body
      const float4 ci4 = *(const float4*)(cibr + k);
      const float4 pi4 = *(const float4*)(pibr + k);
      const float4 w24 = *(const float4*)(w2b + k);
      const float2 fA = __half22float2(*(const __half2*)&v.x);
      const float2 fB = __half22float2(*(const __half2*)&v.y);
      const float ta = fmaf(c2, fA.x, fmaf(c1, pi4.x, ci4.x));
      const float tb = fmaf(c2, fA.y, fmaf(c1, pi4.y, ci4.y));
      const float tc = fmaf(c2, fB.x, fmaf(c1, pi4.z, ci4.z));
      const float td = fmaf(c2, fB.y, fmaf(c1, pi4.w, ci4.w));
      p0 = fmaf(fmaf(ta, tfa(ta), ta), w24.x, p0);
      p1 = fmaf(fmaf(tb, tfa(tb), tb), w24.y, p1);
      p2 = fmaf(fmaf(tc, tfa(tc), tc), w24.z, p2);
      p3 = fmaf(fmaf(td, tfa(td), td), w24.w, p3);
    }
    const float pr = (p0 + p1) + (p2 + p3);
    const float att = fmaf(0.5f, tfa(0.5f * (pr + b2v)), 0.5f);
    S1 = fmaf(att, c1, S1);
    if (val) wkj[r * Nn + idx] = att * c2;
  }
  {
    const float s = wred(S1);
    if (!lane) s1p[w] = s;
  }
  __syncthreads();

  // tail scratch over PtH region (all PtH reads done)
  float* sup8 = smemf;            // [8][64]
  float* supv = smemf + 512;      // [4][64]
  float* h1p  = smemf + 768;      // [8][64]
  float* hm2  = smemf + 1280;     // [4][64]
  float* ot   = smemf + 1536;     // [4][64]

  {
    const int ch = tid >> 6, d = tid & 63;
    const int row = ch & 3, half = ch >> 2;
    const float* xb = x + (size_t)(b * Nn) * 64;
    const int mt = mcnt[row];
    const float* wk = wkj + row * Nn;
    const unsigned short* ji = jidx + row * Nn;
    float a0 = 0.f, a1 = 0.f, a2 = 0.f, a3 = 0.f;
    int p = half;
    for (; p + 6 < mt; p += 8) {
      a0 = fmaf(wk[p],     xb[(size_t)ji[p]     * 64 + d], a0);
      a1 = fmaf(wk[p + 2], xb[(size_t)ji[p + 2] * 64 + d], a1);
      a2 = fmaf(wk[p + 4], xb[(size_t)ji[p + 4] * 64 + d], a2);
      a3 = fmaf(wk[p + 6], xb[(size_t)ji[p + 6] * 64 + d], a3);
    }
    for (; p < mt; p += 2)
      a0 = fmaf(wk[p], xb[(size_t)ji[p] * 64 + d], a0);
    sup8[ch * 64 + d] = (a0 + a1) + (a2 + a3);
  }
  __syncthreads();

  if (tid < 256) {
    const int i2 = tid >> 6, d = tid & 63;
    const int gr_ = b * Nn + i0 + i2;
    const float S1t = (s1p[i2] + s1p[i2 + 4]) + (s1p[i2 + 8] + s1p[i2 + 12]);
    supv[i2 * 64 + d] = fmaf(S1t, x[(size_t)gr_ * 64 + d],
                             sup8[i2 * 64 + d] + sup8[(i2 + 4) * 64 + d]);
  }
  __syncthreads();

  {
    const int ch = tid >> 6, k = tid & 63;
    const int row = ch & 3, half = ch >> 2;
    const int gr_ = b * Nn + i0 + row;
    float acc;
    if (half == 0) {
      acc = mlp_b1[k];
      #pragma unroll 8
      for (int d = 0; d < 64; ++d)
        acc = fmaf(g_uself[(size_t)gr_ * 64 + d], mlp_w1[d * 64 + k], acc);
    } else {
      acc = 0.f;
      #pragma unroll 8
      for (int d = 0; d < 64; ++d)
        acc = fmaf(supv[row * 64 + d], mlp_w1[(64 + d) * 64 + k], acc);
    }
    h1p[ch * 64 + k] = acc;
  }
  __syncthreads();
  if (tid < 256) {
    const int i2 = tid >> 6, k = tid & 63;
    hm2[i2 * 64 + k] = silu_(h1p[i2 * 64 + k] + h1p[(i2 + 4) * 64 + k]);
  }
  __syncthreads();
  if (tid < 256) {
    const int i2 = tid >> 6, k = tid & 63;
    const int gr_ = b * Nn + i0 + i2;
    float o = mlp_b2[k] + g_uself[(size_t)gr_ * 64 + k];
    #pragma unroll 8
    for (int d = 0; d < 64; ++d)
      o = fmaf(hm2[i2 * 64 + d], mlp_w2[d * 64 + k], o);
    ot[i2 * 64 + k] = o;
  }
  __syncthreads();

  if (w < 4) {
    const int gr_ = b * Nn + i0 + w;
    const float a0 = x[(size_t)gr_ * 64 + lane], a1 = x[(size_t)gr_ * 64 + lane + 32];
    const float xx2 = g_y2[gr_];
    const float o0 = ot[w * 64 + lane], o1 = ot[w * 64 + lane + 32];
    const float un = fmaxf(sqrtf(wred(o0 * o0 + o1 * o1)), 1e-15f);
    const float lam = 2.f / fmaxf(1.f - xx2, 1e-15f);
    const float th = tanhf(0.5f * lam * un);
    const float sc = th / un;
    const float sec0 = sc * o0, sec1 = sc * o1;
    const float xy = wred(a0 * sec0 + a1 * sec1);
    const float y2 = wred(sec0 * sec0 + sec1 * sec1);
    const float A = 1.f + 2.f * xy + y2;
    const float Bc = 1.f - xx2;
    const float den = fmaxf(1.f + 2.f * xy + xx2 * y2, 1e-15f);
    const float inv = 1.f / den;
    float r0 = (A * a0 + Bc * sec0) * inv;
    float r1 = (A * a1 + Bc * sec1) * inv;
    const float nrm = fmaxf(sqrtf(wred(r0 * r0 + r1 * r1)), 1e-15f);
    if (nrm > 0.996f) { const float s = 0.996f / nrm; r0 *= s; r1 *= s; }
    float* orow = out + (size_t)gr_ * 64;
    orow[lane] = r0; orow[lane + 32] = r1;
  }
}

extern "C" void kernel_launch(void* const* d_in, const int* in_sizes, int n_in,
                              void* d_out, int out_size)
{
  const float* x      = (const float*)d_in[0];
  const int*   mask   = (const int*)d_in[1];
  const float* att_w1 = (const float*)d_in[2];
  const float* att_b1 = (const float*)d_in[3];
  const float* att_w2 = (const float*)d_in[4];
  const float* att_b2 = (const float*)d_in[5];
  const float* mlp_w1 = (const float*)d_in[6];
  const float* mlp_b1 = (const float*)d_in[7];
  const float* mlp_w2 = (const float*)d_in[8];
  const float* mlp_b2 = (const float*)d_in[9];
  float* out = (float*)d_out;

  cudaFuncSetAttribute(k_main, cudaFuncAttributeMaxDynamicSharedMemorySize,
                       DYN_BYTES);
  k_pre<<<GRAM_BLOCKS + ROW_BLOCKS, 256>>>(x, att_w1, att_b1);
  k_main<<<Bb * (Nn / 4), 512, DYN_BYTES>>>(x, mask, att_w2, att_b2,
                                            mlp_w1, mlp_b1, mlp_w2, mlp_b2, out);
}

// round 13
// speedup vs baseline: 1.2082x; 1.0560x over previous
#include <cuda_runtime.h>
#include <cuda_fp16.h>

#define FULLMASK 0xFFFFFFFFu
constexpr int Bb = 4, Nn = 384, Dd = 64;
constexpr int NR = Bb * Nn;
constexpr int GRAM_BLOCKS = Bb * 12 * 12;   // 576
constexpr int ROW_BLOCKS = NR / 8;          // 192

// dynamic smem layout (float units)
constexpr int PTH_STRIDE = 72;                     // halves per j-row (144 B, 16B-aligned)
constexpr int OFF_PTH  = 0;                        // __half[384][72] = 13824 floats
constexpr int OFF_CIB  = 13824;                    // __half2[4][32] = 128 floats
constexpr int OFF_PIB  = OFF_CIB + 128;            // __half2[4][32] = 128 floats
constexpr int OFF_W2B  = OFF_PIB + 128;            // __half2[32] = 32 floats
constexpr int OFF_WKJ  = OFF_W2B + 32;             // float[4][384] = 1536
constexpr int OFF_JIDX = OFF_WKJ + 1536;           // ushort[4][384] = 768 floats
constexpr int DYN_FLOATS = OFF_JIDX + 768;         // 16416
constexpr int DYN_BYTES = DYN_FLOATS * 4;          // 65,664 B

__device__ float g_y2[NR];
__device__ float g_uself[NR * Dd];
__device__ float g_ci[NR * Dd];    // PRE-HALVED
__device__ float g_P[NR * Dd];     // PRE-HALVED
__device__ float g_gram[(size_t)Bb * Nn * Nn];

__device__ __forceinline__ float wred(float v) {
  #pragma unroll
  for (int o = 16; o > 0; o >>= 1) v += __shfl_xor_sync(FULLMASK, v, o);
  return v;
}
__device__ __forceinline__ float sigm(float x) { return 1.f / (1.f + __expf(-x)); }
__device__ __forceinline__ float silu_(float x) { return x * sigm(x); }
__device__ __forceinline__ float artanh_(float x) {
  x = fminf(x, 1.f - 1e-7f);
  return 0.5f * (log1pf(x) - log1pf(-x));
}
__device__ __forceinline__ float tfa(float x) {
  float y; asm("tanh.approx.f32 %0, %1;" : "=f"(y) : "f"(x)); return y;
}
__device__ __forceinline__ unsigned tanh2u(unsigned x) {
  unsigned y; asm("tanh.approx.f16x2 %0, %1;" : "=r"(y) : "r"(x)); return y;
}
__device__ __forceinline__ unsigned hfma2u(unsigned a, unsigned b, unsigned c) {
  unsigned d;
  asm("fma.rn.f16x2 %0, %1, %2, %3;" : "=r"(d) : "r"(a), "r"(b), "r"(c));
  return d;
}

// ===== k_pre (unchanged) =====
__global__ __launch_bounds__(256)
void k_pre(const float* __restrict__ x,
           const float* __restrict__ att_w1,
           const float* __restrict__ att_b1)
{
  const int tid = threadIdx.x, w = tid >> 5, lane = tid & 31;

  if (blockIdx.x < GRAM_BLOCKS) {
    __shared__ float xis[32][65], xjs[32][65];
    const int t = blockIdx.x;
    const int b = t / 144, rr = t % 144, it = rr / 12, jt = rr % 12;
    const float* xb = x + (size_t)b * Nn * 64;
    for (int e = tid; e < 2048; e += 256) {
      const int r = e >> 6, c = e & 63;
      xis[r][c] = xb[(size_t)(it * 32 + r) * 64 + c];
      xjs[r][c] = xb[(size_t)(jt * 32 + r) * 64 + c];
    }
    __syncthreads();
    const int jj = lane, i4 = w * 4;
    float a0 = 0.f, a1 = 0.f, a2 = 0.f, a3 = 0.f;
    #pragma unroll 16
    for (int k = 0; k < 64; ++k) {
      const float xv = xjs[jj][k];
      a0 = fmaf(xis[i4 + 0][k], xv, a0);
      a1 = fmaf(xis[i4 + 1][k], xv, a1);
      a2 = fmaf(xis[i4 + 2][k], xv, a2);
      a3 = fmaf(xis[i4 + 3][k], xv, a3);
    }
    float* go = g_gram + ((size_t)(b * Nn) + it * 32 + i4) * Nn + jt * 32 + jj;
    go[0] = a0; go[Nn] = a1; go[2 * Nn] = a2; go[3 * Nn] = a3;
    return;
  }

  __shared__ float xis8[8][64];
  __shared__ float us[8][64];
  const int idx = blockIdx.x - GRAM_BLOCKS;
  const int b = idx / 48, i0 = (idx % 48) * 8;
  const float* xb = x + (size_t)b * Nn * 64;

  for (int t = tid; t < 512; t += 256)
    xis8[t >> 6][t & 63] = xb[(size_t)(i0 + (t >> 6)) * 64 + (t & 63)];
  __syncthreads();

  {
    const int r = w, gi = b * Nn + i0 + r;
    const float a0 = xis8[r][lane], a1 = xis8[r][lane + 32];
    const float x2 = wred(a0 * a0 + a1 * a1);
    const float A = 1.f - 2.f * x2 + x2;
    const float Bc = 1.f - x2;
    const float den = fmaxf(1.f - 2.f * x2 + x2 * x2, 1e-15f);
    const float inv = 1.f / den;
    const float s0 = (A * (-a0) + Bc * a0) * inv;
    const float s1 = (A * (-a1) + Bc * a1) * inv;
    const float sn = fmaxf(sqrtf(wred(s0 * s0 + s1 * s1)), 1e-15f);
    const float fac = fmaxf(Bc, 1e-15f);
    const float g = fac * artanh_(sn) / sn;
    us[r][lane] = g * s0; us[r][lane + 32] = g * s1;
    g_uself[(size_t)gi * 64 + lane] = g * s0;
    g_uself[(size_t)gi * 64 + lane + 32] = g * s1;
    if (!lane) g_y2[gi] = x2;
  }
  __syncthreads();

  {
    const int k = tid & 63, rp = tid >> 6;
    float p0 = 0.f, p1 = 0.f, c0 = att_b1[k], c1v = att_b1[k];
    #pragma unroll 8
    for (int d = 0; d < 64; ++d) {
      const float wa = att_w1[d * 64 + k];
      const float wb = att_w1[(64 + d) * 64 + k];
      p0 = fmaf(xis8[rp][d], wa, p0);
      p1 = fmaf(xis8[rp + 4][d], wa, p1);
      c0 = fmaf(us[rp][d], wb, c0);
      c1v = fmaf(us[rp + 4][d], wb, c1v);
    }
    const int g0 = b * Nn + i0 + rp, g1 = g0 + 4;
    g_P[(size_t)g0 * 64 + k] = 0.5f * p0;
    g_P[(size_t)g1 * 64 + k] = 0.5f * p1;
    g_ci[(size_t)g0 * 64 + k] = 0.5f * c0;
    g_ci[(size_t)g1 * 64 + k] = 0.5f * c1v;
  }
}

// ===== k_main: 4 rows/block, 512 threads, full half2 inner loop =====
__global__ __launch_bounds__(512, 2)
void k_main(const float* __restrict__ x,
            const int* __restrict__ mask,
            const float* __restrict__ att_w2,
            const float* __restrict__ att_b2,
            const float* __restrict__ mlp_w1,
            const float* __restrict__ mlp_b1,
            const float* __restrict__ mlp_w2,
            const float* __restrict__ mlp_b2,
            float* __restrict__ out)
{
  extern __shared__ float smemf[];
  __half* PtH = (__half*)(smemf + OFF_PTH);              // [384][72] halves, j-major
  __half2* cib2 = (__half2*)(smemf + OFF_CIB);           // [4][32]
  __half2* pib2 = (__half2*)(smemf + OFF_PIB);           // [4][32]
  __half2* w2b2 = (__half2*)(smemf + OFF_W2B);           // [32]
  float* wkj = smemf + OFF_WKJ;                          // [4][384]
  unsigned short* jidx = (unsigned short*)(smemf + OFF_JIDX); // [4][384]
  __shared__ int mcnt[4];
  __shared__ float s1p[16];

  const int tid = threadIdx.x, w = tid >> 5, lane = tid & 31;
  const int ct = blockIdx.x;
  const int b = ct / 96, i0 = (ct % 96) * 4;
  const int r = w & 3;
  const int gi = b * Nn + i0 + r;
  const float* Pbat = g_P + (size_t)(b * Nn) * 64;

  // ci/Pi/w2 half2 packs (threads 0-127 rows, 128-159 w2)
  if (tid < 128) {
    const int rr = tid >> 5, kp = tid & 31;
    const int gr_ = b * Nn + i0 + rr;
    cib2[rr * 32 + kp] = __floats2half2_rn(g_ci[(size_t)gr_ * 64 + 2 * kp],
                                           g_ci[(size_t)gr_ * 64 + 2 * kp + 1]);
    pib2[rr * 32 + kp] = __floats2half2_rn(g_P[(size_t)gr_ * 64 + 2 * kp],
                                           g_P[(size_t)gr_ * 64 + 2 * kp + 1]);
  } else if (tid < 160) {
    const int kp = tid - 128;
    w2b2[kp] = __floats2half2_rn(att_w2[2 * kp], att_w2[2 * kp + 1]);
  }
  // fp16 tile fill, j-major
  for (int t = tid; t < Nn * 16; t += 512) {
    const int j = t >> 4, k4 = t & 15;
    const float4 pv = *(const float4*)(Pbat + (size_t)j * 64 + k4 * 4);
    const __half2 h0 = __floats2half2_rn(pv.x, pv.y);
    const __half2 h1 = __floats2half2_rn(pv.z, pv.w);
    uint2 st;
    st.x = *(const unsigned*)&h0;
    st.y = *(const unsigned*)&h1;
    *(uint2*)(PtH + j * PTH_STRIDE + k4 * 4) = st;
  }
  if (w < 4) {
    const int* mrow = mask + (size_t)(b * Nn + i0 + w) * Nn;
    int m = 0;
    #pragma unroll
    for (int sub = 0; sub < 12; ++sub) {
      const bool ok = mrow[sub * 32 + lane] != 0;
      const unsigned bal = __ballot_sync(FULLMASK, ok);
      const unsigned pre = bal & ((1u << lane) - 1u);
      if (ok) jidx[w * Nn + m + __popc(pre)] = (unsigned short)(sub * 32 + lane);
      m += __popc(bal);
    }
    if (!lane) mcnt[w] = m;
  }
  __syncthreads();

  const float x2i = g_y2[gi];
  const float omx2 = 1.f - x2i;
  const float fac = fmaxf(omx2, 1e-15f);
  const float b2v = att_b2[0];
  float S1 = 0.f;

  const int m = mcnt[r];
  const uint4* cibr = (const uint4*)(cib2 + r * 32);   // 8 uint4 = 32 half2
  const uint4* pibr = (const uint4*)(pib2 + r * 32);
  const uint4* w2br = (const uint4*)w2b2;
  const float* grow = g_gram + (size_t)gi * Nn;
  const float* y2row = g_y2 + b * Nn;

  for (int g = (w >> 2); g * 32 < m; g += 4) {
    const int idx = g * 32 + lane;
    const bool val = idx < m;
    const int jj = val ? jidx[r * Nn + idx] : 0;
    float c1 = 0.f, c2 = 0.f;
    if (val) {
      const float xy = grow[jj], y2v = y2row[jj];
      const float A = 1.f - 2.f * xy + y2v;
      const float den = fmaxf(fmaf(x2i, y2v, 1.f - 2.f * xy), 1e-15f);
      const float inv = __frcp_rn(den);
      const float t1 = fmaf(A, x2i, -omx2 * xy);
      const float t2 = fmaf(omx2, y2v, -A * xy);
      float sn = sqrtf(fmaxf(inv * inv * fmaf(A, t1, omx2 * t2), 0.f));
      sn = fminf(fmaxf(sn, 1e-15f), 1.f - 1e-7f);
      const float aos = (sn > 1e-3f)
          ? __fdividef(0.5f * __logf((1.f + sn) * __frcp_rn(1.f - sn)), sn)
          : fmaf(sn * sn, 0.33333334f, 1.f);
      const float gg = fac * aos * inv;
      c1 = -gg * A; c2 = gg * omx2;
    }
    const __half2 c1h2 = __float2half2_rn(c1);
    const __half2 c2h2 = __float2half2_rn(c2);
    const unsigned c1u = *(const unsigned*)&c1h2;
    const unsigned c2u = *(const unsigned*)&c2h2;
    const uint4* prow = (const uint4*)(PtH + jj * PTH_STRIDE);  // 8 halves per uint4
    unsigned a0u = 0, a1u = 0, a2u = 0, a3u = 0;   // half2(0,0) accumulators
    #pragma unroll 1
    for (int it = 0; it < 8; ++it) {
      const uint4 pj = prow[it];
      const uint4 ci = cibr[it];
      const uint4 pi = pibr[it];
      const uint4 w2 = w2br[it];
      {
        const unsigned t2 = hfma2u(c2u, pj.x, hfma2u(c1u, pi.x, ci.x));
        a0u = hfma2u(hfma2u(t2, tanh2u(t2), t2), w2.x, a0u);
      }
      {
        const unsigned t2 = hfma2u(c2u, pj.y, hfma2u(c1u, pi.y, ci.y));
        a1u = hfma2u(hfma2u(t2, tanh2u(t2), t2), w2.y, a1u);
      }
      {
        const unsigned t2 = hfma2u(c2u, pj.z, hfma2u(c1u, pi.z, ci.z));
        a2u = hfma2u(hfma2u(t2, tanh2u(t2), t2), w2.z, a2u);
      }
      {
        const unsigned t2 = hfma2u(c2u, pj.w, hfma2u(c1u, pi.w, ci.w));
        a3u = hfma2u(hfma2u(t2, tanh2u(t2), t2), w2.w, a3u);
      }
    }
    const float2 f0 = __half22float2(*(const __half2*)&a0u);
    const float2 f1 = __half22float2(*(const __half2*)&a1u);
    const float2 f2 = __half22float2(*(const __half2*)&a2u);
    const float2 f3 = __half22float2(*(const __half2*)&a3u);
    const float pr = ((f0.x + f0.y) + (f1.x + f1.y))
                   + ((f2.x + f2.y) + (f3.x + f3.y));
    const float att = fmaf(0.5f, tfa(0.5f * (pr + b2v)), 0.5f);
    S1 = fmaf(att, c1, S1);
    if (val) wkj[r * Nn + idx] = att * c2;
  }
  {
    const float s = wred(S1);
    if (!lane) s1p[w] = s;
  }
  __syncthreads();

  // tail scratch over PtH region (all PtH reads done)
  float* sup8 = smemf;            // [8][64]
  float* supv = smemf + 512;      // [4][64]
  float* h1p  = smemf + 768;      // [8][64]
  float* hm2  = smemf + 1280;     // [4][64]
  float* ot   = smemf + 1536;     // [4][64]

  {
    const int ch = tid >> 6, d = tid & 63;
    const int row = ch & 3, half = ch >> 2;
    const float* xb = x + (size_t)(b * Nn) * 64;
    const int mt = mcnt[row];
    const float* wk = wkj + row * Nn;
    const unsigned short* ji = jidx + row * Nn;
    float a0 = 0.f, a1 = 0.f, a2 = 0.f, a3 = 0.f;
    int p = half;
    for (; p + 6 < mt; p += 8) {
      a0 = fmaf(wk[p],     xb[(size_t)ji[p]     * 64 + d], a0);
      a1 = fmaf(wk[p + 2], xb[(size_t)ji[p + 2] * 64 + d], a1);
      a2 = fmaf(wk[p + 4], xb[(size_t)ji[p + 4] * 64 + d], a2);
      a3 = fmaf(wk[p + 6], xb[(size_t)ji[p + 6] * 64 + d], a3);
    }
    for (; p < mt; p += 2)
      a0 = fmaf(wk[p], xb[(size_t)ji[p] * 64 + d], a0);
    sup8[ch * 64 + d] = (a0 + a1) + (a2 + a3);
  }
  __syncthreads();

  if (tid < 256) {
    const int i2 = tid >> 6, d = tid & 63;
    const int gr_ = b * Nn + i0 + i2;
    const float S1t = (s1p[i2] + s1p[i2 + 4]) + (s1p[i2 + 8] + s1p[i2 + 12]);
    supv[i2 * 64 + d] = fmaf(S1t, x[(size_t)gr_ * 64 + d],
                             sup8[i2 * 64 + d] + sup8[(i2 + 4) * 64 + d]);
  }
  __syncthreads();

  {
    const int ch = tid >> 6, k = tid & 63;
    const int row = ch & 3, half = ch >> 2;
    const int gr_ = b * Nn + i0 + row;
    float acc;
    if (half == 0) {
      acc = mlp_b1[k];
      #pragma unroll 8
      for (int d = 0; d < 64; ++d)
        acc = fmaf(g_uself[(size_t)gr_ * 64 + d], mlp_w1[d * 64 + k], acc);
    } else {
      acc = 0.f;
      #pragma unroll 8
      for (int d = 0; d < 64; ++d)
        acc = fmaf(supv[row * 64 + d], mlp_w1[(64 + d) * 64 + k], acc);
    }
    h1p[ch * 64 + k] = acc;
  }
  __syncthreads();
  if (tid < 256) {
    const int i2 = tid >> 6, k = tid & 63;
    hm2[i2 * 64 + k] = silu_(h1p[i2 * 64 + k] + h1p[(i2 + 4) * 64 + k]);
  }
  __syncthreads();
  if (tid < 256) {
    const int i2 = tid >> 6, k = tid & 63;
    const int gr_ = b * Nn + i0 + i2;
    float o = mlp_b2[k] + g_uself[(size_t)gr_ * 64 + k];
    #pragma unroll 8
    for (int d = 0; d < 64; ++d)
      o = fmaf(hm2[i2 * 64 + d], mlp_w2[d * 64 + k], o);
    ot[i2 * 64 + k] = o;
  }
  __syncthreads();

  if (w < 4) {
    const int gr_ = b * Nn + i0 + w;
    const float a0 = x[(size_t)gr_ * 64 + lane], a1 = x[(size_t)gr_ * 64 + lane + 32];
    const float xx2 = g_y2[gr_];
    const float o0 = ot[w * 64 + lane], o1 = ot[w * 64 + lane + 32];
    const float un = fmaxf(sqrtf(wred(o0 * o0 + o1 * o1)), 1e-15f);
    const float lam = 2.f / fmaxf(1.f - xx2, 1e-15f);
    const float th = tanhf(0.5f * lam * un);
    const float sc = th / un;
    const float sec0 = sc * o0, sec1 = sc * o1;
    const float xy = wred(a0 * sec0 + a1 * sec1);
    const float y2 = wred(sec0 * sec0 + sec1 * sec1);
    const float A = 1.f + 2.f * xy + y2;
    const float Bc = 1.f - xx2;
    const float den = fmaxf(1.f + 2.f * xy + xx2 * y2, 1e-15f);
    const float inv = 1.f / den;
    float r0 = (A * a0 + Bc * sec0) * inv;
    float r1 = (A * a1 + Bc * sec1) * inv;
    const float nrm = fmaxf(sqrtf(wred(r0 * r0 + r1 * r1)), 1e-15f);
    if (nrm > 0.996f) { const float s = 0.996f / nrm; r0 *= s; r1 *= s; }
    float* orow = out + (size_t)gr_ * 64;
    orow[lane] = r0; orow[lane + 32] = r1;
  }
}

extern "C" void kernel_launch(void* const* d_in, const int* in_sizes, int n_in,
                              void* d_out, int out_size)
{
  const float* x      = (const float*)d_in[0];
  const int*   mask   = (const int*)d_in[1];
  const float* att_w1 = (const float*)d_in[2];
  const float* att_b1 = (const float*)d_in[3];
  const float* att_w2 = (const float*)d_in[4];
  const float* att_b2 = (const float*)d_in[5];
  const float* mlp_w1 = (const float*)d_in[6];
  const float* mlp_b1 = (const float*)d_in[7];
  const float* mlp_w2 = (const float*)d_in[8];
  const float* mlp_b2 = (const float*)d_in[9];
  float* out = (float*)d_out;

  cudaFuncSetAttribute(k_main, cudaFuncAttributeMaxDynamicSharedMemorySize,
                       DYN_BYTES);
  k_pre<<<GRAM_BLOCKS + ROW_BLOCKS, 256>>>(x, att_w1, att_b1);
  k_main<<<Bb * (Nn / 4), 512, DYN_BYTES>>>(x, mask, att_w2, att_b2,
                                            mlp_w1, mlp_b1, mlp_w2, mlp_b2, out);
}

// round 15
// speedup vs baseline: 1.3525x; 1.1194x over previous
#include <cuda_runtime.h>
#include <cuda_fp16.h>

#define FULLMASK 0xFFFFFFFFu
constexpr int Bb = 4, Nn = 384, Dd = 64;
constexpr int NR = Bb * Nn;
constexpr int GRAM_BLOCKS = Bb * 12 * 12;   // 576
constexpr int ROW_BLOCKS = NR / 8;          // 192

// dynamic smem layout (float units)
constexpr int PTH_STRIDE = 72;                     // halves per j-row (144 B, 16B-aligned)
constexpr int OFF_PTH  = 0;                        // __half[384][72] = 13824 floats
constexpr int OFF_CIB  = 13824;                    // __half2[4][32] = 128 floats
constexpr int OFF_PIB  = OFF_CIB + 128;            // __half2[4][32] = 128 floats
constexpr int OFF_W2B  = OFF_PIB + 128;            // __half2[32] = 32 floats
constexpr int OFF_WKJ  = OFF_W2B + 32;             // float[4][384] = 1536
constexpr int OFF_JIDX = OFF_WKJ + 1536;           // ushort[4][384] = 768 floats
constexpr int DYN_FLOATS = OFF_JIDX + 768;         // 16416
constexpr int DYN_BYTES = DYN_FLOATS * 4;          // 65,664 B

__device__ float g_y2[NR];
__device__ float g_uself[NR * Dd];
__device__ float g_ci[NR * Dd];    // PRE-HALVED
__device__ float g_P[NR * Dd];     // PRE-HALVED
__device__ float g_gram[(size_t)Bb * Nn * Nn];

__device__ __forceinline__ float wred(float v) {
  #pragma unroll
  for (int o = 16; o > 0; o >>= 1) v += __shfl_xor_sync(FULLMASK, v, o);
  return v;
}
__device__ __forceinline__ float sigm(float x) { return 1.f / (1.f + __expf(-x)); }
__device__ __forceinline__ float silu_(float x) { return x * sigm(x); }
__device__ __forceinline__ float artanh_(float x) {
  x = fminf(x, 1.f - 1e-7f);
  return 0.5f * (log1pf(x) - log1pf(-x));
}
__device__ __forceinline__ float tfa(float x) {
  float y; asm("tanh.approx.f32 %0, %1;" : "=f"(y) : "f"(x)); return y;
}
__device__ __forceinline__ unsigned tanh2u(unsigned x) {
  unsigned y; asm("tanh.approx.f16x2 %0, %1;" : "=r"(y) : "r"(x)); return y;
}
__device__ __forceinline__ unsigned hfma2u(unsigned a, unsigned b, unsigned c) {
  unsigned d;
  asm("fma.rn.f16x2 %0, %1, %2, %3;" : "=r"(d) : "r"(a), "r"(b), "r"(c));
  return d;
}

// ===== k_pre (unchanged) =====
__global__ __launch_bounds__(256)
void k_pre(const float* __restrict__ x,
           const float* __restrict__ att_w1,
           const float* __restrict__ att_b1)
{
  const int tid = threadIdx.x, w = tid >> 5, lane = tid & 31;

  if (blockIdx.x < GRAM_BLOCKS) {
    __shared__ float xis[32][65], xjs[32][65];
    const int t = blockIdx.x;
    const int b = t / 144, rr = t % 144, it = rr / 12, jt = rr % 12;
    const float* xb = x + (size_t)b * Nn * 64;
    for (int e = tid; e < 2048; e += 256) {
      const int r = e >> 6, c = e & 63;
      xis[r][c] = xb[(size_t)(it * 32 + r) * 64 + c];
      xjs[r][c] = xb[(size_t)(jt * 32 + r) * 64 + c];
    }
    __syncthreads();
    const int jj = lane, i4 = w * 4;
    float a0 = 0.f, a1 = 0.f, a2 = 0.f, a3 = 0.f;
    #pragma unroll 16
    for (int k = 0; k < 64; ++k) {
      const float xv = xjs[jj][k];
      a0 = fmaf(xis[i4 + 0][k], xv, a0);
      a1 = fmaf(xis[i4 + 1][k], xv, a1);
      a2 = fmaf(xis[i4 + 2][k], xv, a2);
      a3 = fmaf(xis[i4 + 3][k], xv, a3);
    }
    float* go = g_gram + ((size_t)(b * Nn) + it * 32 + i4) * Nn + jt * 32 + jj;
    go[0] = a0; go[Nn] = a1; go[2 * Nn] = a2; go[3 * Nn] = a3;
    return;
  }

  __shared__ float xis8[8][64];
  __shared__ float us[8][64];
  const int idx = blockIdx.x - GRAM_BLOCKS;
  const int b = idx / 48, i0 = (idx % 48) * 8;
  const float* xb = x + (size_t)b * Nn * 64;

  for (int t = tid; t < 512; t += 256)
    xis8[t >> 6][t & 63] = xb[(size_t)(i0 + (t >> 6)) * 64 + (t & 63)];
  __syncthreads();

  {
    const int r = w, gi = b * Nn + i0 + r;
    const float a0 = xis8[r][lane], a1 = xis8[r][lane + 32];
    const float x2 = wred(a0 * a0 + a1 * a1);
    const float A = 1.f - 2.f * x2 + x2;
    const float Bc = 1.f - x2;
    const float den = fmaxf(1.f - 2.f * x2 + x2 * x2, 1e-15f);
    const float inv = 1.f / den;
    const float s0 = (A * (-a0) + Bc * a0) * inv;
    const float s1 = (A * (-a1) + Bc * a1) * inv;
    const float sn = fmaxf(sqrtf(wred(s0 * s0 + s1 * s1)), 1e-15f);
    const float fac = fmaxf(Bc, 1e-15f);
    const float g = fac * artanh_(sn) / sn;
    us[r][lane] = g * s0; us[r][lane + 32] = g * s1;
    g_uself[(size_t)gi * 64 + lane] = g * s0;
    g_uself[(size_t)gi * 64 + lane + 32] = g * s1;
    if (!lane) g_y2[gi] = x2;
  }
  __syncthreads();

  {
    const int k = tid & 63, rp = tid >> 6;
    float p0 = 0.f, p1 = 0.f, c0 = att_b1[k], c1v = att_b1[k];
    #pragma unroll 8
    for (int d = 0; d < 64; ++d) {
      const float wa = att_w1[d * 64 + k];
      const float wb = att_w1[(64 + d) * 64 + k];
      p0 = fmaf(xis8[rp][d], wa, p0);
      p1 = fmaf(xis8[rp + 4][d], wa, p1);
      c0 = fmaf(us[rp][d], wb, c0);
      c1v = fmaf(us[rp + 4][d], wb, c1v);
    }
    const int g0 = b * Nn + i0 + rp, g1 = g0 + 4;
    g_P[(size_t)g0 * 64 + k] = 0.5f * p0;
    g_P[(size_t)g1 * 64 + k] = 0.5f * p1;
    g_ci[(size_t)g0 * 64 + k] = 0.5f * c0;
    g_ci[(size_t)g1 * 64 + k] = 0.5f * c1v;
  }
}

// ===== k_main: 4 rows/block, 512 threads, half2 inner loop, 3 blocks/SM =====
__global__ __launch_bounds__(512, 3)
void k_main(const float* __restrict__ x,
            const int* __restrict__ mask,
            const float* __restrict__ att_w2,
            const float* __restrict__ att_b2,
            const float* __restrict__ mlp_w1,
            const float* __restrict__ mlp_b1,
            const float* __restrict__ mlp_w2,
            const float* __restrict__ mlp_b2,
            float* __restrict__ out)
{
  extern __shared__ float smemf[];
  __half* PtH = (__half*)(smemf + OFF_PTH);              // [384][72] halves, j-major
  __half2* cib2 = (__half2*)(smemf + OFF_CIB);           // [4][32]
  __half2* pib2 = (__half2*)(smemf + OFF_PIB);           // [4][32]
  __half2* w2b2 = (__half2*)(smemf + OFF_W2B);           // [32]
  float* wkj = smemf + OFF_WKJ;                          // [4][384]
  unsigned short* jidx = (unsigned short*)(smemf + OFF_JIDX); // [4][384]
  __shared__ int mcnt[4];
  __shared__ float s1p[16];

  const int tid = threadIdx.x, w = tid >> 5, lane = tid & 31;
  const int ct = blockIdx.x;
  const int b = ct / 96, i0 = (ct % 96) * 4;
  const int r = w & 3;
  const int gi = b * Nn + i0 + r;
  const float* Pbat = g_P + (size_t)(b * Nn) * 64;

  // ci/Pi/w2 half2 packs (threads 0-127 rows, 128-159 w2)
  if (tid < 128) {
    const int rr = tid >> 5, kp = tid & 31;
    const int gr_ = b * Nn + i0 + rr;
    cib2[rr * 32 + kp] = __floats2half2_rn(g_ci[(size_t)gr_ * 64 + 2 * kp],
                                           g_ci[(size_t)gr_ * 64 + 2 * kp + 1]);
    pib2[rr * 32 + kp] = __floats2half2_rn(g_P[(size_t)gr_ * 64 + 2 * kp],
                                           g_P[(size_t)gr_ * 64 + 2 * kp + 1]);
  } else if (tid < 160) {
    const int kp = tid - 128;
    w2b2[kp] = __floats2half2_rn(att_w2[2 * kp], att_w2[2 * kp + 1]);
  }
  // fp16 tile fill, j-major
  for (int t = tid; t < Nn * 16; t += 512) {
    const int j = t >> 4, k4 = t & 15;
    const float4 pv = *(const float4*)(Pbat + (size_t)j * 64 + k4 * 4);
    const __half2 h0 = __floats2half2_rn(pv.x, pv.y);
    const __half2 h1 = __floats2half2_rn(pv.z, pv.w);
    uint2 st;
    st.x = *(const unsigned*)&h0;
    st.y = *(const unsigned*)&h1;
    *(uint2*)(PtH + j * PTH_STRIDE + k4 * 4) = st;
  }
  if (w < 4) {
    const int* mrow = mask + (size_t)(b * Nn + i0 + w) * Nn;
    int m = 0;
    #pragma unroll
    for (int sub = 0; sub < 12; ++sub) {
      const bool ok = mrow[sub * 32 + lane] != 0;
      const unsigned bal = __ballot_sync(FULLMASK, ok);
      const unsigned pre = bal & ((1u << lane) - 1u);
      if (ok) jidx[w * Nn + m + __popc(pre)] = (unsigned short)(sub * 32 + lane);
      m += __popc(bal);
    }
    if (!lane) mcnt[w] = m;
  }
  __syncthreads();

  const float x2i = g_y2[gi];
  const float omx2 = 1.f - x2i;
  const float fac = fmaxf(omx2, 1e-15f);
  const float b2v = att_b2[0];
  float S1 = 0.f;

  const int m = mcnt[r];
  const uint4* cibr = (const uint4*)(cib2 + r * 32);   // 8 uint4 = 32 half2
  const uint4* pibr = (const uint4*)(pib2 + r * 32);
  const uint4* w2br = (const uint4*)w2b2;
  const float* grow = g_gram + (size_t)gi * Nn;
  const float* y2row = g_y2 + b * Nn;

  for (int g = (w >> 2); g * 32 < m; g += 4) {
    const int idx = g * 32 + lane;
    const bool val = idx < m;
    const int jj = val ? jidx[r * Nn + idx] : 0;
    float c1 = 0.f, c2 = 0.f;
    if (val) {
      const float xy = grow[jj], y2v = y2row[jj];
      const float A = 1.f - 2.f * xy + y2v;
      const float den = fmaxf(fmaf(x2i, y2v, 1.f - 2.f * xy), 1e-15f);
      const float inv = __frcp_rn(den);
      const float t1 = fmaf(A, x2i, -omx2 * xy);
      const float t2 = fmaf(omx2, y2v, -A * xy);
      float sn = sqrtf(fmaxf(inv * inv * fmaf(A, t1, omx2 * t2), 0.f));
      sn = fminf(fmaxf(sn, 1e-15f), 1.f - 1e-7f);
      const float aos = (sn > 1e-3f)
          ? __fdividef(0.5f * __logf((1.f + sn) * __frcp_rn(1.f - sn)), sn)
          : fmaf(sn * sn, 0.33333334f, 1.f);
      const float gg = fac * aos * inv;
      c1 = -gg * A; c2 = gg * omx2;
    }
    const __half2 c1h2 = __float2half2_rn(c1);
    const __half2 c2h2 = __float2half2_rn(c2);
    const unsigned c1u = *(const unsigned*)&c1h2;
    const unsigned c2u = *(const unsigned*)&c2h2;
    const uint4* prow = (const uint4*)(PtH + jj * PTH_STRIDE);  // 8 halves per uint4
    unsigned a0u = 0, a1u = 0, a2u = 0, a3u = 0;   // half2(0,0) accumulators
    #pragma unroll 1
    for (int it = 0; it < 8; ++it) {
      const uint4 pj = prow[it];
      const uint4 ci = cibr[it];
      const uint4 pi = pibr[it];
      const uint4 w2 = w2br[it];
      {
        const unsigned t2 = hfma2u(c2u, pj.x, hfma2u(c1u, pi.x, ci.x));
        a0u = hfma2u(hfma2u(t2, tanh2u(t2), t2), w2.x, a0u);
      }
      {
        const unsigned t2 = hfma2u(c2u, pj.y, hfma2u(c1u, pi.y, ci.y));
        a1u = hfma2u(hfma2u(t2, tanh2u(t2), t2), w2.y, a1u);
      }
      {
        const unsigned t2 = hfma2u(c2u, pj.z, hfma2u(c1u, pi.z, ci.z));
        a2u = hfma2u(hfma2u(t2, tanh2u(t2), t2), w2.z, a2u);
      }
      {
        const unsigned t2 = hfma2u(c2u, pj.w, hfma2u(c1u, pi.w, ci.w));
        a3u = hfma2u(hfma2u(t2, tanh2u(t2), t2), w2.w, a3u);
      }
    }
    const float2 f0 = __half22float2(*(const __half2*)&a0u);
    const float2 f1 = __half22float2(*(const __half2*)&a1u);
    const float2 f2 = __half22float2(*(const __half2*)&a2u);
    const float2 f3 = __half22float2(*(const __half2*)&a3u);
    const float pr = ((f0.x + f0.y) + (f1.x + f1.y))
                   + ((f2.x + f2.y) + (f3.x + f3.y));
    const float att = fmaf(0.5f, tfa(0.5f * (pr + b2v)), 0.5f);
    S1 = fmaf(att, c1, S1);
    if (val) wkj[r * Nn + idx] = att * c2;
  }
  {
    const float s = wred(S1);
    if (!lane) s1p[w] = s;
  }
  __syncthreads();

  // tail scratch over PtH region (all PtH reads done)
  float* sup8 = smemf;            // [8][64]
  float* supv = smemf + 512;      // [4][64]
  float* h1p  = smemf + 768;      // [8][64]
  float* hm2  = smemf + 1280;     // [4][64]
  float* ot   = smemf + 1536;     // [4][64]

  {
    const int ch = tid >> 6, d = tid & 63;
    const int row = ch & 3, half = ch >> 2;
    const float* xb = x + (size_t)(b * Nn) * 64;
    const int mt = mcnt[row];
    const float* wk = wkj + row * Nn;
    const unsigned short* ji = jidx + row * Nn;
    float a0 = 0.f, a1 = 0.f, a2 = 0.f, a3 = 0.f;
    int p = half;
    for (; p + 6 < mt; p += 8) {
      a0 = fmaf(wk[p],     xb[(size_t)ji[p]     * 64 + d], a0);
      a1 = fmaf(wk[p + 2], xb[(size_t)ji[p + 2] * 64 + d], a1);
      a2 = fmaf(wk[p + 4], xb[(size_t)ji[p + 4] * 64 + d], a2);
      a3 = fmaf(wk[p + 6], xb[(size_t)ji[p + 6] * 64 + d], a3);
    }
    for (; p < mt; p += 2)
      a0 = fmaf(wk[p], xb[(size_t)ji[p] * 64 + d], a0);
    sup8[ch * 64 + d] = (a0 + a1) + (a2 + a3);
  }
  __syncthreads();

  if (tid < 256) {
    const int i2 = tid >> 6, d = tid & 63;
    const int gr_ = b * Nn + i0 + i2;
    const float S1t = (s1p[i2] + s1p[i2 + 4]) + (s1p[i2 + 8] + s1p[i2 + 12]);
    supv[i2 * 64 + d] = fmaf(S1t, x[(size_t)gr_ * 64 + d],
                             sup8[i2 * 64 + d] + sup8[(i2 + 4) * 64 + d]);
  }
  __syncthreads();

  {
    const int ch = tid >> 6, k = tid & 63;
    const int row = ch & 3, half = ch >> 2;
    const int gr_ = b * Nn + i0 + row;
    float acc;
    if (half == 0) {
      acc = mlp_b1[k];
      #pragma unroll 8
      for (int d = 0; d < 64; ++d)
        acc = fmaf(g_uself[(size_t)gr_ * 64 + d], mlp_w1[d * 64 + k], acc);
    } else {
      acc = 0.f;
      #pragma unroll 8
      for (int d = 0; d < 64; ++d)
        acc = fmaf(supv[row * 64 + d], mlp_w1[(64 + d) * 64 + k], acc);
    }
    h1p[ch * 64 + k] = acc;
  }
  __syncthreads();
  if (tid < 256) {
    const int i2 = tid >> 6, k = tid & 63;
    hm2[i2 * 64 + k] = silu_(h1p[i2 * 64 + k] + h1p[(i2 + 4) * 64 + k]);
  }
  __syncthreads();
  if (tid < 256) {
    const int i2 = tid >> 6, k = tid & 63;
    const int gr_ = b * Nn + i0 + i2;
    float o = mlp_b2[k] + g_uself[(size_t)gr_ * 64 + k];
    #pragma unroll 8
    for (int d = 0; d < 64; ++d)
      o = fmaf(hm2[i2 * 64 + d], mlp_w2[d * 64 + k], o);
    ot[i2 * 64 + k] = o;
  }
  __syncthreads();

  if (w < 4) {
    const int gr_ = b * Nn + i0 + w;
    const float a0 = x[(size_t)gr_ * 64 + lane], a1 = x[(size_t)gr_ * 64 + lane + 32];
    const float xx2 = g_y2[gr_];
    const float o0 = ot[w * 64 + lane], o1 = ot[w * 64 + lane + 32];
    const float un = fmaxf(sqrtf(wred(o0 * o0 + o1 * o1)), 1e-15f);
    const float lam = 2.f / fmaxf(1.f - xx2, 1e-15f);
    const float th = tanhf(0.5f * lam * un);
    const float sc = th / un;
    const float sec0 = sc * o0, sec1 = sc * o1;
    const float xy = wred(a0 * sec0 + a1 * sec1);
    const float y2 = wred(sec0 * sec0 + sec1 * sec1);
    const float A = 1.f + 2.f * xy + y2;
    const float Bc = 1.f - xx2;
    const float den = fmaxf(1.f + 2.f * xy + xx2 * y2, 1e-15f);
    const float inv = 1.f / den;
    float r0 = (A * a0 + Bc * sec0) * inv;
    float r1 = (A * a1 + Bc * sec1) * inv;
    const float nrm = fmaxf(sqrtf(wred(r0 * r0 + r1 * r1)), 1e-15f);
    if (nrm > 0.996f) { const float s = 0.996f / nrm; r0 *= s; r1 *= s; }
    float* orow = out + (size_t)gr_ * 64;
    orow[lane] = r0; orow[lane + 32] = r1;
  }
}

extern "C" void kernel_launch(void* const* d_in, const int* in_sizes, int n_in,
                              void* d_out, int out_size)
{
  const float* x      = (const float*)d_in[0];
  const int*   mask   = (const int*)d_in[1];
  const float* att_w1 = (const float*)d_in[2];
  const float* att_b1 = (const float*)d_in[3];
  const float* att_w2 = (const float*)d_in[4];
  const float* att_b2 = (const float*)d_in[5];
  const float* mlp_w1 = (const float*)d_in[6];
  const float* mlp_b1 = (const float*)d_in[7];
  const float* mlp_w2 = (const float*)d_in[8];
  const float* mlp_b2 = (const float*)d_in[9];
  float* out = (float*)d_out;

  cudaFuncSetAttribute(k_main, cudaFuncAttributeMaxDynamicSharedMemorySize,
                       DYN_BYTES);
  k_pre<<<GRAM_BLOCKS + ROW_BLOCKS, 256>>>(x, att_w1, att_b1);
  k_main<<<Bb * (Nn / 4), 512, DYN_BYTES>>>(x, mask, att_w2, att_b2,
                                            mlp_w1, mlp_b1, mlp_w2, mlp_b2, out);
}